// round 11
// baseline (speedup 1.0000x reference)
#include <cuda_runtime.h>
#include <cuda_bf16.h>
#include <cstdint>
#include <math.h>

#define B     64
#define LA    8
#define H     512
#define V     16384
#define SS    316
#define CTXN  256
#define NROWS (B*LA)
#define SCALE 0.04419417382415922f   // 512^-0.5
#define NZROWS 60
#define MAXNZ  16

// ---------------- device scratch ----------------
__device__ __align__(16) float g_gen_exp[(size_t)NROWS * V];
__device__ float g_copy_exp[NROWS * SS];
__device__ float g_rowsum[NROWS];
__device__ __align__(16) __nv_bfloat16 g_Abf[NROWS * H];       // dec bf16
__device__ __align__(16) __nv_bfloat16 g_Wt[(size_t)V * H];    // W^T bf16, K-major
__device__ int2 g_nz[NZROWS * B * MAXNZ];                      // (v, fp32 bits)
__device__ int  g_nzc[NZROWS * B];

// ---------------- helpers ----------------
__device__ __forceinline__ uint32_t smem_u32(const void* p) {
    uint32_t a;
    asm("{ .reg .u64 t; cvta.to.shared.u64 t, %1; cvt.u32.u64 %0, t; }" : "=r"(a) : "l"(p));
    return a;
}
__device__ __forceinline__ void ldmx4(uint32_t* r, uint32_t addr) {
    asm volatile("ldmatrix.sync.aligned.m8n8.x4.shared.b16 {%0,%1,%2,%3}, [%4];"
        : "=r"(r[0]), "=r"(r[1]), "=r"(r[2]), "=r"(r[3]) : "r"(addr));
}
__device__ __forceinline__ void mma16816(float* d, const uint32_t* a, uint32_t b0, uint32_t b1) {
    asm volatile("mma.sync.aligned.m16n8k16.row.col.f32.bf16.bf16.f32 "
        "{%0,%1,%2,%3}, {%4,%5,%6,%7}, {%8,%9}, {%0,%1,%2,%3};"
        : "+f"(d[0]), "+f"(d[1]), "+f"(d[2]), "+f"(d[3])
        : "r"(a[0]), "r"(a[1]), "r"(a[2]), "r"(a[3]), "r"(b0), "r"(b1));
}
__device__ __forceinline__ void cp_async16(uint32_t dst, const void* src) {
    asm volatile("cp.async.cg.shared.global [%0], [%1], 16;" :: "r"(dst), "l"(src));
}
#define CP_COMMIT() asm volatile("cp.async.commit_group;")
#define CP_WAIT(n)  asm volatile("cp.async.wait_group %0;" :: "n"(n))

__device__ __forceinline__ float4 ldcs4(const float* p) {
    float4 v;
    asm volatile("ld.global.cs.v4.f32 {%0,%1,%2,%3}, [%4];"
        : "=f"(v.x), "=f"(v.y), "=f"(v.z), "=f"(v.w) : "l"(p));
    return v;
}

// ---------------- Kc_A: dec fp32 -> bf16 (+ zero rowsums) ----------------
__global__ void kc_A(const float* __restrict__ dec) {
    int i = blockIdx.x * 256 + threadIdx.x;
    g_Abf[i] = __float2bfloat16(dec[i]);
    if (i < NROWS) g_rowsum[i] = 0.f;
}

// ---------------- Kc_W: W[K,V] -> Wt[V,K] bf16 ----------------
__global__ __launch_bounds__(256) void kc_W(const float* __restrict__ W) {
    __shared__ float t[64][33];
    int n0 = blockIdx.x * 32, k0 = blockIdx.y * 64;
    int tx = threadIdx.x & 31, ty = threadIdx.x >> 5;
    for (int i = ty; i < 64; i += 8)
        t[i][tx] = W[(size_t)(k0 + i) * V + n0 + tx];
    __syncthreads();
    for (int i = ty; i < 32; i += 8) {
        __nv_bfloat162 h2;
        h2.x = __float2bfloat16(t[2 * tx][i]);
        h2.y = __float2bfloat16(t[2 * tx + 1][i]);
        *(__nv_bfloat162*)&g_Wt[(size_t)(n0 + i) * H + k0 + 2 * tx] = h2;
    }
}

// ================== MEGA kernel: GEMM + scan + copy-logits ==================
#define PITCH 40
#define STG 3
#define TILE_HALFS (128 * PITCH)
#define K2_SMEM (STG * 2 * TILE_HALFS * 2)  // 61440 B dynamic
#define N_GEMM 512
#define N_SCAN (NZROWS * B)                 // 3840
#define N_K1   (B * 3)                      // 192
#define N_MEGA 4544                         // 512 + 3840 + 192

// ---- GEMM body (128 threads, warp tile 64x64, CTA 128x128, BK=32) ----
__device__ __forceinline__ void gemm_body(int gid, const float* __restrict__ bias,
                                          __nv_bfloat16* sm) {
    __nv_bfloat16* As = sm;
    __nv_bfloat16* Bs = sm + STG * TILE_HALFS;

    int tid = threadIdx.x, wid = tid >> 5, lane = tid & 31;
    int bx = gid & 127, by = gid >> 7;
    int wm = wid >> 1, wn = wid & 1;

    const __nv_bfloat16* Ag = g_Abf + (size_t)(by * 128) * H;
    const __nv_bfloat16* Bg = g_Wt + (size_t)(bx * 128) * H;

    float acc[4][8][4];
    #pragma unroll
    for (int i = 0; i < 4; i++)
        #pragma unroll
        for (int j = 0; j < 8; j++)
            #pragma unroll
            for (int k = 0; k < 4; k++) acc[i][j][k] = 0.f;

    int ldr = tid >> 2, ldc8 = (tid & 3) * 8;

    #define ISSUE(KT, BUF) do {                                                       \
        _Pragma("unroll")                                                              \
        for (int q = 0; q < 4; q++) {                                                  \
            int _r = ldr + 32 * q;                                                     \
            cp_async16(smem_u32(&As[(BUF) * TILE_HALFS + _r * PITCH + ldc8]),          \
                       Ag + (size_t)_r * H + (KT) * 32 + ldc8);                        \
            cp_async16(smem_u32(&Bs[(BUF) * TILE_HALFS + _r * PITCH + ldc8]),          \
                       Bg + (size_t)_r * H + (KT) * 32 + ldc8);                        \
        }                                                                              \
        CP_COMMIT();                                                                   \
    } while (0)

    ISSUE(0, 0); ISSUE(1, 1);

    int g = lane >> 3, r = lane & 7;
    uint32_t a0[4], b0[4];
    #pragma unroll
    for (int mt = 0; mt < 4; mt++)
        a0[mt] = smem_u32(&As[(wm * 64 + mt * 16 + (g & 1) * 8 + r) * PITCH + (g >> 1) * 8]);
    #pragma unroll
    for (int nq = 0; nq < 4; nq++)
        b0[nq] = smem_u32(&Bs[(wn * 64 + nq * 16 + (g >> 1) * 8 + r) * PITCH + (g & 1) * 8]);

    for (int kt = 0; kt < 16; kt++) {
        if (kt < 15) CP_WAIT(1); else CP_WAIT(0);
        __syncthreads();
        if (kt + 2 < 16) ISSUE(kt + 2, (kt + 2) % STG);

        uint32_t soff = (uint32_t)(kt % STG) * (TILE_HALFS * 2);
        #pragma unroll
        for (int kk = 0; kk < 2; kk++) {
            uint32_t ko = soff + kk * 32;
            uint32_t afr[4][4];
            #pragma unroll
            for (int mt = 0; mt < 4; mt++) ldmx4(afr[mt], a0[mt] + ko);
            uint32_t bfr[4][4];
            #pragma unroll
            for (int nq = 0; nq < 4; nq++) ldmx4(bfr[nq], b0[nq] + ko);
            #pragma unroll
            for (int mt = 0; mt < 4; mt++)
                #pragma unroll
                for (int nt = 0; nt < 8; nt++)
                    mma16816(acc[mt][nt], afr[mt],
                             bfr[nt >> 1][(nt & 1) * 2], bfr[nt >> 1][(nt & 1) * 2 + 1]);
        }
    }

    int r4 = lane >> 2, c2 = (lane & 3) * 2;
    #pragma unroll
    for (int mt = 0; mt < 4; mt++) {
        float rs0 = 0.f, rs1 = 0.f;
        #pragma unroll
        for (int nt = 0; nt < 8; nt++) {
            int col = bx * 128 + wn * 64 + nt * 8 + c2;
            float b0f = bias[col], b1f = bias[col + 1];
            int row0 = by * 128 + wm * 64 + mt * 16 + r4;
            float e0 = __expf((acc[mt][nt][0] + b0f) * SCALE);
            float e1 = __expf((acc[mt][nt][1] + b1f) * SCALE);
            *(float2*)&g_gen_exp[(size_t)row0 * V + col] = make_float2(e0, e1);
            rs0 += e0 + e1;
            float e2 = __expf((acc[mt][nt][2] + b0f) * SCALE);
            float e3 = __expf((acc[mt][nt][3] + b1f) * SCALE);
            *(float2*)&g_gen_exp[(size_t)(row0 + 8) * V + col] = make_float2(e2, e3);
            rs1 += e2 + e3;
        }
        #pragma unroll
        for (int off = 1; off < 4; off <<= 1) {
            rs0 += __shfl_xor_sync(0xffffffffu, rs0, off);
            rs1 += __shfl_xor_sync(0xffffffffu, rs1, off);
        }
        if ((lane & 3) == 0) {
            int row0 = by * 128 + wm * 64 + mt * 16 + r4;
            atomicAdd(&g_rowsum[row0], rs0);
            atomicAdd(&g_rowsum[row0 + 8], rs1);
        }
    }
}

// ---- scan body (128 threads): one-hot row -> compact nz list ----
__device__ __forceinline__ void scan_body(int rid, const float* __restrict__ pv,
                                          const float* __restrict__ lmat,
                                          const float* __restrict__ tpm,
                                          const float* __restrict__ rel,
                                          int* scnt) {
    int b = rid & (B - 1), row = rid >> 6;
    int tid = threadIdx.x;
    if (tid == 0) *scnt = 0;
    __syncthreads();

    const float* base;
    int p, np;
    if (row < 10)      { base = pv;   p = row;      np = 10; }
    else if (row < 20) { base = lmat; p = row - 10; np = 10; }
    else if (row < 30) { base = tpm;  p = row - 20; np = 10; }
    else               { base = rel;  p = row - 30; np = 30; }
    const float* mrow = base + ((size_t)b * np + p) * V;

    #pragma unroll 8
    for (int q = 0; q < 32; q++) {
        int v4 = q * 128 + tid;
        float4 m = ldcs4(&mrow[(size_t)v4 * 4]);
        float mv[4] = {m.x, m.y, m.z, m.w};
        #pragma unroll
        for (int c = 0; c < 4; c++) {
            if (mv[c] != 0.f) {
                int pos = atomicAdd(scnt, 1);
                if (pos < MAXNZ)
                    g_nz[rid * MAXNZ + pos] = make_int2(v4 * 4 + c, __float_as_int(mv[c]));
            }
        }
    }
    __syncthreads();
    if (tid == 0) g_nzc[rid] = (*scnt < MAXNZ) ? *scnt : MAXNZ;
}

// ---- k1 body (128 threads): copy logits for 128 s-positions of one b ----
__device__ __forceinline__ void k1_body(int j, const float* __restrict__ dec,
                                        const float* __restrict__ srch,
                                        const int* __restrict__ mask,
                                        float4* dsm, float* lsum) {
    int b = j & (B - 1), chunk = j >> 6;     // chunk 0..2
    int tid = threadIdx.x;
    const float4* dg = (const float4*)(dec + (size_t)b * LA * H);
    for (int i = tid; i < LA * H / 4; i += 128)
        dsm[i] = dg[i];
    if (tid < LA) lsum[tid] = 0.f;
    __syncthreads();

    int s = chunk * 128 + tid;
    bool valid = (s < SS);
    int m = valid ? mask[b * SS + s] : 0;

    float acc[LA];
    #pragma unroll
    for (int l = 0; l < LA; l++) acc[l] = 0.f;

    if (m != 0) {
        const float4* vp = (const float4*)(srch + ((size_t)b * SS + s) * H);
        #pragma unroll 8
        for (int h4 = 0; h4 < H / 4; h4 += 2) {
            float4 v0 = vp[h4], v1 = vp[h4 + 1];
            #pragma unroll
            for (int l = 0; l < LA; l++) {
                float4 d0 = dsm[l * (H / 4) + h4];
                acc[l] += d0.x * v0.x + d0.y * v0.y + d0.z * v0.z + d0.w * v0.w;
                float4 d1 = dsm[l * (H / 4) + h4 + 1];
                acc[l] += d1.x * v1.x + d1.y * v1.y + d1.z * v1.z + d1.w * v1.w;
            }
        }
    }

    #pragma unroll
    for (int l = 0; l < LA; l++) {
        float e = (m != 0) ? __expf(acc[l] * SCALE) : 0.f;
        if (valid) g_copy_exp[(b * LA + l) * SS + s] = e;
        float r = e;
        #pragma unroll
        for (int off = 16; off; off >>= 1) r += __shfl_xor_sync(0xffffffffu, r, off);
        if ((tid & 31) == 0) atomicAdd(&lsum[l], r);
    }
    __syncthreads();
    if (tid < LA) atomicAdd(&g_rowsum[b * LA + tid], lsum[tid]);
}

// ---- dispatch ----
__global__ __launch_bounds__(128) void k_mega(const float* __restrict__ bias,
                                              const float* __restrict__ dec,
                                              const float* __restrict__ srch,
                                              const int* __restrict__ mask,
                                              const float* __restrict__ pv,
                                              const float* __restrict__ lmat,
                                              const float* __restrict__ tpm,
                                              const float* __restrict__ rel) {
    extern __shared__ __align__(16) __nv_bfloat16 dynsm[];
    __shared__ float small[LA];
    __shared__ int scnt;

    int bi = blockIdx.x;
    if (bi < 4096 && (bi & 7) == 0) {
        gemm_body(bi >> 3, bias, dynsm);
        return;
    }
    int id = (bi < 4096) ? (bi - (bi >> 3) - 1) : (bi - N_GEMM);
    if (id < N_SCAN) {
        scan_body(id, pv, lmat, tpm, rel, &scnt);
    } else {
        k1_body(id - N_SCAN, dec, srch, mask, (float4*)dynsm, small);
    }
}

// ---------------- K_apply: scatter copy_exp into g_gen_exp (unnormalized) -
__global__ __launch_bounds__(256) void k_apply(const int* __restrict__ ctx,
                                               const int* __restrict__ g2l) {
    int blk = blockIdx.x, tid = threadIdx.x;
    if (blk < 15) {
        int rid = blk * 256 + tid;
        if (rid >= NZROWS * B) return;
        int b = rid & (B - 1), row = rid >> 6;
        int src = (row < 30) ? row : row + CTXN;
        int cnt = g_nzc[rid];
        for (int j = 0; j < cnt; j++) {
            int2 e = g_nz[rid * MAXNZ + j];
            float val = __int_as_float(e.y);
            #pragma unroll
            for (int l = 0; l < LA; l++)
                atomicAdd(&g_gen_exp[(size_t)(b * LA + l) * V + e.x],
                          g_copy_exp[(b * LA + l) * SS + src] * val);
        }
    } else {
        int b = blk - 15;
        int tgt = g2l[ctx[b * CTXN + tid]];
        #pragma unroll
        for (int l = 0; l < LA; l++)
            atomicAdd(&g_gen_exp[(size_t)(b * LA + l) * V + tgt],
                      g_copy_exp[(b * LA + l) * SS + 30 + tid]);
    }
}

// ---------------- K4n: out = g_gen_exp * invZ ----------------------------
__global__ __launch_bounds__(256) void k4_norm(float* __restrict__ out) {
    int row = blockIdx.x;
    __shared__ float zs;
    if (threadIdx.x == 0) zs = 1.f / g_rowsum[row];
    __syncthreads();
    float z = zs;
    const float* src = &g_gen_exp[(size_t)row * V];
    float4* dst = (float4*)&out[(size_t)row * V];
    #pragma unroll 4
    for (int i = threadIdx.x; i < V / 4; i += 256) {
        float4 v = ldcs4(src + i * 4);
        v.x *= z; v.y *= z; v.z *= z; v.w *= z;
        dst[i] = v;
    }
}

// ---------------- launch (single stream) ----------------------------------
extern "C" void kernel_launch(void* const* d_in, const int* in_sizes, int n_in,
                              void* d_out, int out_size) {
    const float* dec  = (const float*)d_in[0];
    const float* srch = (const float*)d_in[1];
    const int*   mask = (const int*)  d_in[2];
    const float* pv   = (const float*)d_in[3];
    const float* lmat = (const float*)d_in[4];
    const float* tpm  = (const float*)d_in[5];
    const float* rel  = (const float*)d_in[6];
    const float* W    = (const float*)d_in[7];
    const float* bias = (const float*)d_in[8];
    const int*   ctx  = (const int*)  d_in[9];
    const int*   g2l  = (const int*)  d_in[10];
    float* out = (float*)d_out;

    cudaFuncSetAttribute(k_mega, cudaFuncAttributeMaxDynamicSharedMemorySize, K2_SMEM);

    kc_A<<<NROWS * H / 256, 256>>>(dec);
    kc_W<<<dim3(V / 32, H / 64), 256>>>(W);
    k_mega<<<N_MEGA, 128, K2_SMEM>>>(bias, dec, srch, mask, pv, lmat, tpm, rel);
    k_apply<<<79, 256>>>(ctx, g2l);
    k4_norm<<<NROWS, 256>>>(out);
}

// round 12
// speedup vs baseline: 1.7102x; 1.7102x over previous
#include <cuda_runtime.h>
#include <cuda_bf16.h>
#include <cstdint>
#include <math.h>

#define B     64
#define LA    8
#define H     512
#define V     16384
#define SS    316
#define CTXN  256
#define NROWS (B*LA)
#define SCALE 0.04419417382415922f   // 512^-0.5
#define NZROWS 60
#define MAXNZ  16

// ---------------- device scratch ----------------
__device__ __align__(16) float g_gen_exp[(size_t)NROWS * V];
__device__ float g_copy_exp[NROWS * SS];
__device__ __align__(16) float g_rs_gen[NROWS * 256];   // per-(row, bx*2+wn) partials
__device__ float g_rs_copy[B * 2 * LA];                 // per-(b, chunk, l) partials
__device__ __align__(16) __nv_bfloat16 g_Abf[NROWS * H];
__device__ __align__(16) __nv_bfloat16 g_Wt[(size_t)V * H];
__device__ int2 g_nz[NZROWS * B * MAXNZ];
__device__ int  g_nzc[NZROWS * B];

// ---------------- helpers ----------------
__device__ __forceinline__ uint32_t smem_u32(const void* p) {
    uint32_t a;
    asm("{ .reg .u64 t; cvta.to.shared.u64 t, %1; cvt.u32.u64 %0, t; }" : "=r"(a) : "l"(p));
    return a;
}
__device__ __forceinline__ void ldmx4(uint32_t* r, uint32_t addr) {
    asm volatile("ldmatrix.sync.aligned.m8n8.x4.shared.b16 {%0,%1,%2,%3}, [%4];"
        : "=r"(r[0]), "=r"(r[1]), "=r"(r[2]), "=r"(r[3]) : "r"(addr));
}
__device__ __forceinline__ void mma16816(float* d, const uint32_t* a, uint32_t b0, uint32_t b1) {
    asm volatile("mma.sync.aligned.m16n8k16.row.col.f32.bf16.bf16.f32 "
        "{%0,%1,%2,%3}, {%4,%5,%6,%7}, {%8,%9}, {%0,%1,%2,%3};"
        : "+f"(d[0]), "+f"(d[1]), "+f"(d[2]), "+f"(d[3])
        : "r"(a[0]), "r"(a[1]), "r"(a[2]), "r"(a[3]), "r"(b0), "r"(b1));
}
__device__ __forceinline__ void cp_async16(uint32_t dst, const void* src) {
    asm volatile("cp.async.cg.shared.global [%0], [%1], 16;" :: "r"(dst), "l"(src));
}
#define CP_COMMIT() asm volatile("cp.async.commit_group;")
#define CP_WAIT(n)  asm volatile("cp.async.wait_group %0;" :: "n"(n))

__device__ __forceinline__ float4 ldcs4(const float* p) {
    float4 v;
    asm volatile("ld.global.cs.v4.f32 {%0,%1,%2,%3}, [%4];"
        : "=f"(v.x), "=f"(v.y), "=f"(v.z), "=f"(v.w) : "l"(p));
    return v;
}

// ================== PREP kernel: k1 + kc_A + kc_W + scan ==================
// grid: [0,128) k1 | [128,384) kc_A | [384,4480) kc_W | [4480,8320) scan
#define NP_K1   128
#define NP_KCA  256
#define NP_KCW  4096
#define NP_SCAN (NZROWS * B)
#define N_PREP  (NP_K1 + NP_KCA + NP_KCW + NP_SCAN)   // 8320

// ---- k1: copy logits for one (b, chunk of 158 s) ----
__device__ __forceinline__ void k1_body(int j, const float* __restrict__ dec,
                                        const float* __restrict__ srch,
                                        const int* __restrict__ mask,
                                        float4* dsm, float* lsum) {
    int b = j >> 1, chunk = j & 1;
    int tid = threadIdx.x;
    const float4* dg = (const float4*)(dec + (size_t)b * LA * H);
    for (int i = tid; i < LA * H / 4; i += 256) dsm[i] = dg[i];
    if (tid < LA) lsum[tid] = 0.f;
    __syncthreads();

    int s = chunk * 158 + tid;
    bool valid = (tid < 158);
    int m = valid ? mask[b * SS + s] : 0;

    float acc[LA];
    #pragma unroll
    for (int l = 0; l < LA; l++) acc[l] = 0.f;

    if (m != 0) {
        const float4* vp = (const float4*)(srch + ((size_t)b * SS + s) * H);
        #pragma unroll 8
        for (int h4 = 0; h4 < H / 4; h4 += 2) {
            float4 v0 = vp[h4], v1 = vp[h4 + 1];
            #pragma unroll
            for (int l = 0; l < LA; l++) {
                float4 d0 = dsm[l * (H / 4) + h4];
                acc[l] += d0.x * v0.x + d0.y * v0.y + d0.z * v0.z + d0.w * v0.w;
                float4 d1 = dsm[l * (H / 4) + h4 + 1];
                acc[l] += d1.x * v1.x + d1.y * v1.y + d1.z * v1.z + d1.w * v1.w;
            }
        }
    }

    #pragma unroll
    for (int l = 0; l < LA; l++) {
        float e = (m != 0) ? __expf(acc[l] * SCALE) : 0.f;
        if (valid) g_copy_exp[(b * LA + l) * SS + s] = e;
        float r = e;
        #pragma unroll
        for (int off = 16; off; off >>= 1) r += __shfl_xor_sync(0xffffffffu, r, off);
        if ((tid & 31) == 0) atomicAdd(&lsum[l], r);
    }
    __syncthreads();
    if (tid < LA) g_rs_copy[(b * 2 + chunk) * LA + tid] = lsum[tid];
}

// ---- kc_A: dec -> bf16, 1024 elems per block ----
__device__ __forceinline__ void kcA_body(int j, const float* __restrict__ dec) {
    int i = j * 1024 + threadIdx.x * 4;
    float4 v = *(const float4*)&dec[i];
    __nv_bfloat162 h0, h1;
    h0.x = __float2bfloat16(v.x); h0.y = __float2bfloat16(v.y);
    h1.x = __float2bfloat16(v.z); h1.y = __float2bfloat16(v.w);
    *(__nv_bfloat162*)&g_Abf[i] = h0;
    *(__nv_bfloat162*)&g_Abf[i + 2] = h1;
}

// ---- kc_W: 32(n) x 64(k) transpose tile ----
__device__ __forceinline__ void kcW_body(int j, const float* __restrict__ W, float* t) {
    // t: [64][33]
    int n0 = (j & 511) * 32, k0 = (j >> 9) * 64;
    int tx = threadIdx.x & 31, ty = threadIdx.x >> 5;
    for (int i = ty; i < 64; i += 8)
        t[i * 33 + tx] = W[(size_t)(k0 + i) * V + n0 + tx];
    __syncthreads();
    for (int i = ty; i < 32; i += 8) {
        __nv_bfloat162 h2;
        h2.x = __float2bfloat16(t[(2 * tx) * 33 + i]);
        h2.y = __float2bfloat16(t[(2 * tx + 1) * 33 + i]);
        *(__nv_bfloat162*)&g_Wt[(size_t)(n0 + i) * H + k0 + 2 * tx] = h2;
    }
}

// ---- scan: one-hot row -> compact nz list ----
__device__ __forceinline__ void scan_body(int rid, const float* __restrict__ pv,
                                          const float* __restrict__ lmat,
                                          const float* __restrict__ tpm,
                                          const float* __restrict__ rel,
                                          int* scnt) {
    int b = rid & (B - 1), row = rid >> 6;
    int tid = threadIdx.x;
    if (tid == 0) *scnt = 0;
    __syncthreads();

    const float* base;
    int p, np;
    if (row < 10)      { base = pv;   p = row;      np = 10; }
    else if (row < 20) { base = lmat; p = row - 10; np = 10; }
    else if (row < 30) { base = tpm;  p = row - 20; np = 10; }
    else               { base = rel;  p = row - 30; np = 30; }
    const float* mrow = base + ((size_t)b * np + p) * V;

    #pragma unroll
    for (int q = 0; q < 16; q++) {
        int v4 = q * 256 + tid;
        float4 m = ldcs4(&mrow[(size_t)v4 * 4]);
        float mv[4] = {m.x, m.y, m.z, m.w};
        #pragma unroll
        for (int c = 0; c < 4; c++) {
            if (mv[c] != 0.f) {
                int pos = atomicAdd(scnt, 1);
                if (pos < MAXNZ)
                    g_nz[rid * MAXNZ + pos] = make_int2(v4 * 4 + c, __float_as_int(mv[c]));
            }
        }
    }
    __syncthreads();
    if (tid == 0) g_nzc[rid] = (*scnt < MAXNZ) ? *scnt : MAXNZ;
}

__global__ __launch_bounds__(256) void k_prep(const float* __restrict__ dec,
                                              const float* __restrict__ srch,
                                              const int* __restrict__ mask,
                                              const float* __restrict__ W,
                                              const float* __restrict__ pv,
                                              const float* __restrict__ lmat,
                                              const float* __restrict__ tpm,
                                              const float* __restrict__ rel) {
    __shared__ __align__(16) unsigned char usm[16384];   // k1: 16KB, kcW: 8.4KB
    __shared__ float lsum[LA];
    __shared__ int scnt;

    int bi = blockIdx.x;
    if (bi < NP_K1) {
        k1_body(bi, dec, srch, mask, (float4*)usm, lsum);
    } else if (bi < NP_K1 + NP_KCA) {
        kcA_body(bi - NP_K1, dec);
    } else if (bi < NP_K1 + NP_KCA + NP_KCW) {
        kcW_body(bi - NP_K1 - NP_KCA, W, (float*)usm);
    } else {
        scan_body(bi - NP_K1 - NP_KCA - NP_KCW, pv, lmat, tpm, rel, &scnt);
    }
}

// ---------------- K2: warp-MMA bf16 GEMM, warp tile 64x64 -----------------
#define PITCH 40
#define STG 3
#define TILE_HALFS (128 * PITCH)
#define K2_SMEM (STG * 2 * TILE_HALFS * 2)  // 61440 B
__global__ __launch_bounds__(128) void k2m(const float* __restrict__ bias) {
    extern __shared__ __align__(16) __nv_bfloat16 sm[];
    __nv_bfloat16* As = sm;
    __nv_bfloat16* Bs = sm + STG * TILE_HALFS;

    int tid = threadIdx.x, wid = tid >> 5, lane = tid & 31;
    int bx = blockIdx.x, by = blockIdx.y;
    int wm = wid >> 1, wn = wid & 1;

    const __nv_bfloat16* Ag = g_Abf + (size_t)(by * 128) * H;
    const __nv_bfloat16* Bg = g_Wt + (size_t)(bx * 128) * H;

    float acc[4][8][4];
    #pragma unroll
    for (int i = 0; i < 4; i++)
        #pragma unroll
        for (int j = 0; j < 8; j++)
            #pragma unroll
            for (int k = 0; k < 4; k++) acc[i][j][k] = 0.f;

    int ldr = tid >> 2, ldc8 = (tid & 3) * 8;

    #define ISSUE(KT, BUF) do {                                                       \
        _Pragma("unroll")                                                              \
        for (int q = 0; q < 4; q++) {                                                  \
            int _r = ldr + 32 * q;                                                     \
            cp_async16(smem_u32(&As[(BUF) * TILE_HALFS + _r * PITCH + ldc8]),          \
                       Ag + (size_t)_r * H + (KT) * 32 + ldc8);                        \
            cp_async16(smem_u32(&Bs[(BUF) * TILE_HALFS + _r * PITCH + ldc8]),          \
                       Bg + (size_t)_r * H + (KT) * 32 + ldc8);                        \
        }                                                                              \
        CP_COMMIT();                                                                   \
    } while (0)

    ISSUE(0, 0); ISSUE(1, 1);

    int g = lane >> 3, r = lane & 7;
    uint32_t a0[4], b0[4];
    #pragma unroll
    for (int mt = 0; mt < 4; mt++)
        a0[mt] = smem_u32(&As[(wm * 64 + mt * 16 + (g & 1) * 8 + r) * PITCH + (g >> 1) * 8]);
    #pragma unroll
    for (int nq = 0; nq < 4; nq++)
        b0[nq] = smem_u32(&Bs[(wn * 64 + nq * 16 + (g >> 1) * 8 + r) * PITCH + (g & 1) * 8]);

    for (int kt = 0; kt < 16; kt++) {
        if (kt < 15) CP_WAIT(1); else CP_WAIT(0);
        __syncthreads();
        if (kt + 2 < 16) ISSUE(kt + 2, (kt + 2) % STG);

        uint32_t soff = (uint32_t)(kt % STG) * (TILE_HALFS * 2);
        #pragma unroll
        for (int kk = 0; kk < 2; kk++) {
            uint32_t ko = soff + kk * 32;
            uint32_t afr[4][4];
            #pragma unroll
            for (int mt = 0; mt < 4; mt++) ldmx4(afr[mt], a0[mt] + ko);
            uint32_t bfr[4][4];
            #pragma unroll
            for (int nq = 0; nq < 4; nq++) ldmx4(bfr[nq], b0[nq] + ko);
            #pragma unroll
            for (int mt = 0; mt < 4; mt++)
                #pragma unroll
                for (int nt = 0; nt < 8; nt++)
                    mma16816(acc[mt][nt], afr[mt],
                             bfr[nt >> 1][(nt & 1) * 2], bfr[nt >> 1][(nt & 1) * 2 + 1]);
        }
    }

    // epilogue: bias + exp (unnormalized) + plain-store rowsum partials
    int r4 = lane >> 2, c2 = (lane & 3) * 2;
    #pragma unroll
    for (int mt = 0; mt < 4; mt++) {
        float rs0 = 0.f, rs1 = 0.f;
        #pragma unroll
        for (int nt = 0; nt < 8; nt++) {
            int col = bx * 128 + wn * 64 + nt * 8 + c2;
            float b0f = bias[col], b1f = bias[col + 1];
            int row0 = by * 128 + wm * 64 + mt * 16 + r4;
            float e0 = __expf((acc[mt][nt][0] + b0f) * SCALE);
            float e1 = __expf((acc[mt][nt][1] + b1f) * SCALE);
            *(float2*)&g_gen_exp[(size_t)row0 * V + col] = make_float2(e0, e1);
            rs0 += e0 + e1;
            float e2 = __expf((acc[mt][nt][2] + b0f) * SCALE);
            float e3 = __expf((acc[mt][nt][3] + b1f) * SCALE);
            *(float2*)&g_gen_exp[(size_t)(row0 + 8) * V + col] = make_float2(e2, e3);
            rs1 += e2 + e3;
        }
        #pragma unroll
        for (int off = 1; off < 4; off <<= 1) {
            rs0 += __shfl_xor_sync(0xffffffffu, rs0, off);
            rs1 += __shfl_xor_sync(0xffffffffu, rs1, off);
        }
        if ((lane & 3) == 0) {
            int row0 = by * 128 + wm * 64 + mt * 16 + r4;
            g_rs_gen[row0 * 256 + bx * 2 + wn] = rs0;
            g_rs_gen[(row0 + 8) * 256 + bx * 2 + wn] = rs1;
        }
    }
}

// ---------------- K_apply: scatter copy_exp into g_gen_exp (unnormalized) -
__global__ __launch_bounds__(256) void k_apply(const int* __restrict__ ctx,
                                               const int* __restrict__ g2l) {
    int blk = blockIdx.x, tid = threadIdx.x;
    if (blk < 15) {
        int rid = blk * 256 + tid;
        if (rid >= NZROWS * B) return;
        int b = rid & (B - 1), row = rid >> 6;
        int src = (row < 30) ? row : row + CTXN;
        int cnt = g_nzc[rid];
        for (int j = 0; j < cnt; j++) {
            int2 e = g_nz[rid * MAXNZ + j];
            float val = __int_as_float(e.y);
            #pragma unroll
            for (int l = 0; l < LA; l++)
                atomicAdd(&g_gen_exp[(size_t)(b * LA + l) * V + e.x],
                          g_copy_exp[(b * LA + l) * SS + src] * val);
        }
    } else {
        int b = blk - 15;
        int tgt = g2l[ctx[b * CTXN + tid]];
        #pragma unroll
        for (int l = 0; l < LA; l++)
            atomicAdd(&g_gen_exp[(size_t)(b * LA + l) * V + tgt],
                      g_copy_exp[(b * LA + l) * SS + 30 + tid]);
    }
}

// ---------------- K4n: reduce rowsum partials, out = g_gen_exp * invZ -----
__global__ __launch_bounds__(256) void k4_norm(float* __restrict__ out) {
    __shared__ float red[8];
    __shared__ float zs;
    int row = blockIdx.x;
    int b = row >> 3, l = row & 7;
    int tid = threadIdx.x, lane = tid & 31, wrp = tid >> 5;

    float t = g_rs_gen[row * 256 + tid];
    if (tid < 2) t += g_rs_copy[(b * 2 + tid) * LA + l];
    #pragma unroll
    for (int off = 16; off; off >>= 1) t += __shfl_xor_sync(0xffffffffu, t, off);
    if (lane == 0) red[wrp] = t;
    __syncthreads();
    if (tid == 0) {
        float z = 0.f;
        #pragma unroll
        for (int j = 0; j < 8; j++) z += red[j];
        zs = 1.f / z;
    }
    __syncthreads();
    float z = zs;

    const float* src = &g_gen_exp[(size_t)row * V];
    float4* dst = (float4*)&out[(size_t)row * V];
    #pragma unroll 4
    for (int i = tid; i < V / 4; i += 256) {
        float4 v = ldcs4(src + i * 4);
        v.x *= z; v.y *= z; v.z *= z; v.w *= z;
        dst[i] = v;
    }
}

// ---------------- launch (single stream, 4 kernels) ------------------------
extern "C" void kernel_launch(void* const* d_in, const int* in_sizes, int n_in,
                              void* d_out, int out_size) {
    const float* dec  = (const float*)d_in[0];
    const float* srch = (const float*)d_in[1];
    const int*   mask = (const int*)  d_in[2];
    const float* pv   = (const float*)d_in[3];
    const float* lmat = (const float*)d_in[4];
    const float* tpm  = (const float*)d_in[5];
    const float* rel  = (const float*)d_in[6];
    const float* W    = (const float*)d_in[7];
    const float* bias = (const float*)d_in[8];
    const int*   ctx  = (const int*)  d_in[9];
    const int*   g2l  = (const int*)  d_in[10];
    float* out = (float*)d_out;

    cudaFuncSetAttribute(k2m, cudaFuncAttributeMaxDynamicSharedMemorySize, K2_SMEM);

    k_prep<<<N_PREP, 256>>>(dec, srch, mask, W, pv, lmat, tpm, rel);
    k2m<<<dim3(V / 128, NROWS / 128), 128, K2_SMEM>>>(bias);
    k_apply<<<79, 256>>>(ctx, g2l);
    k4_norm<<<NROWS, 256>>>(out);
}

// round 13
// speedup vs baseline: 1.7559x; 1.0267x over previous
#include <cuda_runtime.h>
#include <cuda_bf16.h>
#include <cstdint>
#include <math.h>

#define B     64
#define LA    8
#define H     512
#define V     16384
#define SS    316
#define CTXN  256
#define NROWS (B*LA)
#define SCALE 0.04419417382415922f   // 512^-0.5
#define NZROWS 60
#define MAXNZ  16

// ---------------- device scratch ----------------
__device__ __align__(16) float g_gen_exp[(size_t)NROWS * V];
__device__ float g_copy_exp[NROWS * SS];
__device__ __align__(16) float g_rs_gen[NROWS * 256];   // per-(row, bx*2+wn) partials
__device__ float g_rs_copy[B * 2 * LA];                 // per-(b, chunk, l) partials
__device__ float g_rowsum[NROWS];                       // stores 1/Z after k_apply
__device__ __align__(16) __nv_bfloat16 g_Abf[NROWS * H];
__device__ __align__(16) __nv_bfloat16 g_Wt[(size_t)V * H];
__device__ int2 g_nz[NZROWS * B * MAXNZ];
__device__ int  g_nzc[NZROWS * B];

// ---------------- helpers ----------------
__device__ __forceinline__ uint32_t smem_u32(const void* p) {
    uint32_t a;
    asm("{ .reg .u64 t; cvta.to.shared.u64 t, %1; cvt.u32.u64 %0, t; }" : "=r"(a) : "l"(p));
    return a;
}
__device__ __forceinline__ void ldmx4(uint32_t* r, uint32_t addr) {
    asm volatile("ldmatrix.sync.aligned.m8n8.x4.shared.b16 {%0,%1,%2,%3}, [%4];"
        : "=r"(r[0]), "=r"(r[1]), "=r"(r[2]), "=r"(r[3]) : "r"(addr));
}
__device__ __forceinline__ void mma16816(float* d, const uint32_t* a, uint32_t b0, uint32_t b1) {
    asm volatile("mma.sync.aligned.m16n8k16.row.col.f32.bf16.bf16.f32 "
        "{%0,%1,%2,%3}, {%4,%5,%6,%7}, {%8,%9}, {%0,%1,%2,%3};"
        : "+f"(d[0]), "+f"(d[1]), "+f"(d[2]), "+f"(d[3])
        : "r"(a[0]), "r"(a[1]), "r"(a[2]), "r"(a[3]), "r"(b0), "r"(b1));
}
__device__ __forceinline__ void cp_async16(uint32_t dst, const void* src) {
    asm volatile("cp.async.cg.shared.global [%0], [%1], 16;" :: "r"(dst), "l"(src));
}
#define CP_COMMIT() asm volatile("cp.async.commit_group;")
#define CP_WAIT(n)  asm volatile("cp.async.wait_group %0;" :: "n"(n))

__device__ __forceinline__ float4 ldcs4(const float* p) {
    float4 v;
    asm volatile("ld.global.cs.v4.f32 {%0,%1,%2,%3}, [%4];"
        : "=f"(v.x), "=f"(v.y), "=f"(v.z), "=f"(v.w) : "l"(p));
    return v;
}

// ================== PREP kernel: k1 + kc_A + kc_W + scan ==================
#define NP_K1   128
#define NP_KCA  256
#define NP_KCW  4096
#define NP_SCAN (NZROWS * B)
#define N_PREP  (NP_K1 + NP_KCA + NP_KCW + NP_SCAN)   // 8320

__device__ __forceinline__ void k1_body(int j, const float* __restrict__ dec,
                                        const float* __restrict__ srch,
                                        const int* __restrict__ mask,
                                        float4* dsm, float* lsum) {
    int b = j >> 1, chunk = j & 1;
    int tid = threadIdx.x;
    const float4* dg = (const float4*)(dec + (size_t)b * LA * H);
    for (int i = tid; i < LA * H / 4; i += 256) dsm[i] = dg[i];
    if (tid < LA) lsum[tid] = 0.f;
    __syncthreads();

    int s = chunk * 158 + tid;
    bool valid = (tid < 158);
    int m = valid ? mask[b * SS + s] : 0;

    float acc[LA];
    #pragma unroll
    for (int l = 0; l < LA; l++) acc[l] = 0.f;

    if (m != 0) {
        const float4* vp = (const float4*)(srch + ((size_t)b * SS + s) * H);
        #pragma unroll 8
        for (int h4 = 0; h4 < H / 4; h4 += 2) {
            float4 v0 = vp[h4], v1 = vp[h4 + 1];
            #pragma unroll
            for (int l = 0; l < LA; l++) {
                float4 d0 = dsm[l * (H / 4) + h4];
                acc[l] += d0.x * v0.x + d0.y * v0.y + d0.z * v0.z + d0.w * v0.w;
                float4 d1 = dsm[l * (H / 4) + h4 + 1];
                acc[l] += d1.x * v1.x + d1.y * v1.y + d1.z * v1.z + d1.w * v1.w;
            }
        }
    }

    #pragma unroll
    for (int l = 0; l < LA; l++) {
        float e = (m != 0) ? __expf(acc[l] * SCALE) : 0.f;
        if (valid) g_copy_exp[(b * LA + l) * SS + s] = e;
        float r = e;
        #pragma unroll
        for (int off = 16; off; off >>= 1) r += __shfl_xor_sync(0xffffffffu, r, off);
        if ((tid & 31) == 0) atomicAdd(&lsum[l], r);
    }
    __syncthreads();
    if (tid < LA) g_rs_copy[(b * 2 + chunk) * LA + tid] = lsum[tid];
}

__device__ __forceinline__ void kcA_body(int j, const float* __restrict__ dec) {
    int i = j * 1024 + threadIdx.x * 4;
    float4 v = *(const float4*)&dec[i];
    __nv_bfloat162 h0, h1;
    h0.x = __float2bfloat16(v.x); h0.y = __float2bfloat16(v.y);
    h1.x = __float2bfloat16(v.z); h1.y = __float2bfloat16(v.w);
    *(__nv_bfloat162*)&g_Abf[i] = h0;
    *(__nv_bfloat162*)&g_Abf[i + 2] = h1;
}

__device__ __forceinline__ void kcW_body(int j, const float* __restrict__ W, float* t) {
    int n0 = (j & 511) * 32, k0 = (j >> 9) * 64;
    int tx = threadIdx.x & 31, ty = threadIdx.x >> 5;
    for (int i = ty; i < 64; i += 8)
        t[i * 33 + tx] = W[(size_t)(k0 + i) * V + n0 + tx];
    __syncthreads();
    for (int i = ty; i < 32; i += 8) {
        __nv_bfloat162 h2;
        h2.x = __float2bfloat16(t[(2 * tx) * 33 + i]);
        h2.y = __float2bfloat16(t[(2 * tx + 1) * 33 + i]);
        *(__nv_bfloat162*)&g_Wt[(size_t)(n0 + i) * H + k0 + 2 * tx] = h2;
    }
}

__device__ __forceinline__ void scan_body(int rid, const float* __restrict__ pv,
                                          const float* __restrict__ lmat,
                                          const float* __restrict__ tpm,
                                          const float* __restrict__ rel,
                                          int* scnt) {
    int b = rid & (B - 1), row = rid >> 6;
    int tid = threadIdx.x;
    if (tid == 0) *scnt = 0;
    __syncthreads();

    const float* base;
    int p, np;
    if (row < 10)      { base = pv;   p = row;      np = 10; }
    else if (row < 20) { base = lmat; p = row - 10; np = 10; }
    else if (row < 30) { base = tpm;  p = row - 20; np = 10; }
    else               { base = rel;  p = row - 30; np = 30; }
    const float* mrow = base + ((size_t)b * np + p) * V;

    #pragma unroll
    for (int q = 0; q < 16; q++) {
        int v4 = q * 256 + tid;
        float4 m = ldcs4(&mrow[(size_t)v4 * 4]);
        float mv[4] = {m.x, m.y, m.z, m.w};
        #pragma unroll
        for (int c = 0; c < 4; c++) {
            if (mv[c] != 0.f) {
                int pos = atomicAdd(scnt, 1);
                if (pos < MAXNZ)
                    g_nz[rid * MAXNZ + pos] = make_int2(v4 * 4 + c, __float_as_int(mv[c]));
            }
        }
    }
    __syncthreads();
    if (tid == 0) g_nzc[rid] = (*scnt < MAXNZ) ? *scnt : MAXNZ;
}

__global__ __launch_bounds__(256) void k_prep(const float* __restrict__ dec,
                                              const float* __restrict__ srch,
                                              const int* __restrict__ mask,
                                              const float* __restrict__ W,
                                              const float* __restrict__ pv,
                                              const float* __restrict__ lmat,
                                              const float* __restrict__ tpm,
                                              const float* __restrict__ rel) {
    __shared__ __align__(16) unsigned char usm[16384];
    __shared__ float lsum[LA];
    __shared__ int scnt;

    int bi = blockIdx.x;
    if (bi < NP_K1) {
        k1_body(bi, dec, srch, mask, (float4*)usm, lsum);
    } else if (bi < NP_K1 + NP_KCA) {
        kcA_body(bi - NP_K1, dec);
    } else if (bi < NP_K1 + NP_KCA + NP_KCW) {
        kcW_body(bi - NP_K1 - NP_KCA, W, (float*)usm);
    } else {
        scan_body(bi - NP_K1 - NP_KCA - NP_KCW, pv, lmat, tpm, rel, &scnt);
    }
}

// ---------------- K2: warp-MMA bf16 GEMM, warp tile 64x64 -----------------
#define PITCH 40
#define STG 3
#define TILE_HALFS (128 * PITCH)
#define K2_SMEM (STG * 2 * TILE_HALFS * 2)  // 61440 B
__global__ __launch_bounds__(128) void k2m(const float* __restrict__ bias) {
    extern __shared__ __align__(16) __nv_bfloat16 sm[];
    __nv_bfloat16* As = sm;
    __nv_bfloat16* Bs = sm + STG * TILE_HALFS;

    int tid = threadIdx.x, wid = tid >> 5, lane = tid & 31;
    int bx = blockIdx.x, by = blockIdx.y;
    int wm = wid >> 1, wn = wid & 1;

    const __nv_bfloat16* Ag = g_Abf + (size_t)(by * 128) * H;
    const __nv_bfloat16* Bg = g_Wt + (size_t)(bx * 128) * H;

    float acc[4][8][4];
    #pragma unroll
    for (int i = 0; i < 4; i++)
        #pragma unroll
        for (int j = 0; j < 8; j++)
            #pragma unroll
            for (int k = 0; k < 4; k++) acc[i][j][k] = 0.f;

    int ldr = tid >> 2, ldc8 = (tid & 3) * 8;

    #define ISSUE(KT, BUF) do {                                                       \
        _Pragma("unroll")                                                              \
        for (int q = 0; q < 4; q++) {                                                  \
            int _r = ldr + 32 * q;                                                     \
            cp_async16(smem_u32(&As[(BUF) * TILE_HALFS + _r * PITCH + ldc8]),          \
                       Ag + (size_t)_r * H + (KT) * 32 + ldc8);                        \
            cp_async16(smem_u32(&Bs[(BUF) * TILE_HALFS + _r * PITCH + ldc8]),          \
                       Bg + (size_t)_r * H + (KT) * 32 + ldc8);                        \
        }                                                                              \
        CP_COMMIT();                                                                   \
    } while (0)

    ISSUE(0, 0); ISSUE(1, 1);

    int g = lane >> 3, r = lane & 7;
    uint32_t a0[4], b0[4];
    #pragma unroll
    for (int mt = 0; mt < 4; mt++)
        a0[mt] = smem_u32(&As[(wm * 64 + mt * 16 + (g & 1) * 8 + r) * PITCH + (g >> 1) * 8]);
    #pragma unroll
    for (int nq = 0; nq < 4; nq++)
        b0[nq] = smem_u32(&Bs[(wn * 64 + nq * 16 + (g >> 1) * 8 + r) * PITCH + (g & 1) * 8]);

    for (int kt = 0; kt < 16; kt++) {
        if (kt < 15) CP_WAIT(1); else CP_WAIT(0);
        __syncthreads();
        if (kt + 2 < 16) ISSUE(kt + 2, (kt + 2) % STG);

        uint32_t soff = (uint32_t)(kt % STG) * (TILE_HALFS * 2);
        #pragma unroll
        for (int kk = 0; kk < 2; kk++) {
            uint32_t ko = soff + kk * 32;
            uint32_t afr[4][4];
            #pragma unroll
            for (int mt = 0; mt < 4; mt++) ldmx4(afr[mt], a0[mt] + ko);
            uint32_t bfr[4][4];
            #pragma unroll
            for (int nq = 0; nq < 4; nq++) ldmx4(bfr[nq], b0[nq] + ko);
            #pragma unroll
            for (int mt = 0; mt < 4; mt++)
                #pragma unroll
                for (int nt = 0; nt < 8; nt++)
                    mma16816(acc[mt][nt], afr[mt],
                             bfr[nt >> 1][(nt & 1) * 2], bfr[nt >> 1][(nt & 1) * 2 + 1]);
        }
    }

    int r4 = lane >> 2, c2 = (lane & 3) * 2;
    #pragma unroll
    for (int mt = 0; mt < 4; mt++) {
        float rs0 = 0.f, rs1 = 0.f;
        #pragma unroll
        for (int nt = 0; nt < 8; nt++) {
            int col = bx * 128 + wn * 64 + nt * 8 + c2;
            float b0f = bias[col], b1f = bias[col + 1];
            int row0 = by * 128 + wm * 64 + mt * 16 + r4;
            float e0 = __expf((acc[mt][nt][0] + b0f) * SCALE);
            float e1 = __expf((acc[mt][nt][1] + b1f) * SCALE);
            *(float2*)&g_gen_exp[(size_t)row0 * V + col] = make_float2(e0, e1);
            rs0 += e0 + e1;
            float e2 = __expf((acc[mt][nt][2] + b0f) * SCALE);
            float e3 = __expf((acc[mt][nt][3] + b1f) * SCALE);
            *(float2*)&g_gen_exp[(size_t)(row0 + 8) * V + col] = make_float2(e2, e3);
            rs1 += e2 + e3;
        }
        #pragma unroll
        for (int off = 1; off < 4; off <<= 1) {
            rs0 += __shfl_xor_sync(0xffffffffu, rs0, off);
            rs1 += __shfl_xor_sync(0xffffffffu, rs1, off);
        }
        if ((lane & 3) == 0) {
            int row0 = by * 128 + wm * 64 + mt * 16 + r4;
            g_rs_gen[row0 * 256 + bx * 2 + wn] = rs0;
            g_rs_gen[(row0 + 8) * 256 + bx * 2 + wn] = rs1;
        }
    }
}

// ---------------- K_apply: scatter (wide) + invZ reduction -----------------
// grid 696: [0,512) ctx scatter (block per output row)
//           [512,632) one-hot scatter (32 rids x 8 l per block)
//           [632,696) invZ: warp per row reduces 256+2 partials -> g_rowsum=1/Z
__global__ __launch_bounds__(256) void k_apply(const int* __restrict__ ctx,
                                               const int* __restrict__ g2l) {
    int blk = blockIdx.x, tid = threadIdx.x;
    if (blk < 512) {
        int row = blk, b = row >> 3;
        int tgt = g2l[ctx[b * CTXN + tid]];
        atomicAdd(&g_gen_exp[(size_t)row * V + tgt], g_copy_exp[row * SS + 30 + tid]);
    } else if (blk < 632) {
        int j = blk - 512;
        int rid = j * 32 + (tid >> 3);
        int l = tid & 7;
        int b = rid & (B - 1), r60 = rid >> 6;
        int src = (r60 < 30) ? r60 : r60 + CTXN;
        int row = b * LA + l;
        float pc = g_copy_exp[row * SS + src];
        int cnt = g_nzc[rid];
        for (int q = 0; q < cnt; q++) {
            int2 e = g_nz[rid * MAXNZ + q];
            atomicAdd(&g_gen_exp[(size_t)row * V + e.x], pc * __int_as_float(e.y));
        }
    } else {
        int j = blk - 632;
        int wrp = tid >> 5, lane = tid & 31;
        int row = j * 8 + wrp;
        int b = row >> 3, l = row & 7;
        float t = 0.f;
        #pragma unroll
        for (int q = 0; q < 8; q++) t += g_rs_gen[row * 256 + q * 32 + lane];
        if (lane < 2) t += g_rs_copy[(b * 2 + lane) * LA + l];
        #pragma unroll
        for (int off = 16; off; off >>= 1) t += __shfl_xor_sync(0xffffffffu, t, off);
        if (lane == 0) g_rowsum[row] = 1.f / t;
    }
}

// ---------------- K4n: out = g_gen_exp * invZ (4 blocks per row) ----------
__global__ __launch_bounds__(256) void k4_norm(float* __restrict__ out) {
    int row = blockIdx.x >> 2, seg = blockIdx.x & 3;
    float z = g_rowsum[row];
    const float* src = &g_gen_exp[(size_t)row * V + seg * (V / 4)];
    float4* dst = (float4*)&out[(size_t)row * V + seg * (V / 4)];
    #pragma unroll
    for (int i = threadIdx.x; i < V / 16; i += 256) {
        float4 v = ldcs4(src + i * 4);
        v.x *= z; v.y *= z; v.z *= z; v.w *= z;
        dst[i] = v;
    }
}

// ---------------- launch (single stream, 4 kernels) ------------------------
extern "C" void kernel_launch(void* const* d_in, const int* in_sizes, int n_in,
                              void* d_out, int out_size) {
    const float* dec  = (const float*)d_in[0];
    const float* srch = (const float*)d_in[1];
    const int*   mask = (const int*)  d_in[2];
    const float* pv   = (const float*)d_in[3];
    const float* lmat = (const float*)d_in[4];
    const float* tpm  = (const float*)d_in[5];
    const float* rel  = (const float*)d_in[6];
    const float* W    = (const float*)d_in[7];
    const float* bias = (const float*)d_in[8];
    const int*   ctx  = (const int*)  d_in[9];
    const int*   g2l  = (const int*)  d_in[10];
    float* out = (float*)d_out;

    cudaFuncSetAttribute(k2m, cudaFuncAttributeMaxDynamicSharedMemorySize, K2_SMEM);

    k_prep<<<N_PREP, 256>>>(dec, srch, mask, W, pv, lmat, tpm, rel);
    k2m<<<dim3(V / 128, NROWS / 128), 128, K2_SMEM>>>(bias);
    k_apply<<<696, 256>>>(ctx, g2l);
    k4_norm<<<NROWS * 4, 256>>>(out);
}

// round 14
// speedup vs baseline: 1.9892x; 1.1328x over previous
#include <cuda_runtime.h>
#include <cuda_bf16.h>
#include <cstdint>
#include <math.h>

#define B     64
#define LA    8
#define H     512
#define V     16384
#define SS    316
#define CTXN  256
#define NROWS (B*LA)
#define SCALE 0.04419417382415922f   // 512^-0.5
#define NZROWS 60
#define MAXNZ  16
#define N_TILES 512
#define GEMM_GRID 296                // 2 CTAs/SM single wave

// ---------------- device scratch ----------------
__device__ __align__(16) float g_gen_exp[(size_t)NROWS * V];
__device__ float g_copy_exp[NROWS * SS];
__device__ __align__(16) float g_rs_gen[NROWS * 256];
__device__ float g_rs_copy[B * 2 * LA];
__device__ float g_rowsum[NROWS];    // holds 1/Z after k_apply
__device__ __align__(16) __nv_bfloat16 g_Abf[NROWS * H];
__device__ __align__(16) __nv_bfloat16 g_Wt[(size_t)V * H];
__device__ int2 g_nz[NZROWS * B * MAXNZ];
__device__ int  g_nzc[NZROWS * B];

// ---------------- helpers ----------------
__device__ __forceinline__ uint32_t smem_u32(const void* p) {
    uint32_t a;
    asm("{ .reg .u64 t; cvta.to.shared.u64 t, %1; cvt.u32.u64 %0, t; }" : "=r"(a) : "l"(p));
    return a;
}
__device__ __forceinline__ void ldmx4(uint32_t* r, uint32_t addr) {
    asm volatile("ldmatrix.sync.aligned.m8n8.x4.shared.b16 {%0,%1,%2,%3}, [%4];"
        : "=r"(r[0]), "=r"(r[1]), "=r"(r[2]), "=r"(r[3]) : "r"(addr));
}
__device__ __forceinline__ void mma16816(float* d, const uint32_t* a, uint32_t b0, uint32_t b1) {
    asm volatile("mma.sync.aligned.m16n8k16.row.col.f32.bf16.bf16.f32 "
        "{%0,%1,%2,%3}, {%4,%5,%6,%7}, {%8,%9}, {%0,%1,%2,%3};"
        : "+f"(d[0]), "+f"(d[1]), "+f"(d[2]), "+f"(d[3])
        : "r"(a[0]), "r"(a[1]), "r"(a[2]), "r"(a[3]), "r"(b0), "r"(b1));
}
__device__ __forceinline__ void cp_async16(uint32_t dst, const void* src) {
    asm volatile("cp.async.cg.shared.global [%0], [%1], 16;" :: "r"(dst), "l"(src));
}
#define CP_COMMIT() asm volatile("cp.async.commit_group;")
#define CP_WAIT(n)  asm volatile("cp.async.wait_group %0;" :: "n"(n))

__device__ __forceinline__ float4 ldcs4(const float* p) {
    float4 v;
    asm volatile("ld.global.cs.v4.f32 {%0,%1,%2,%3}, [%4];"
        : "=f"(v.x), "=f"(v.y), "=f"(v.z), "=f"(v.w) : "l"(p));
    return v;
}

// ================== PREP0 kernel: kc_A + kc_W + k1 ==================
#define NP_K1   128
#define NP_KCA  256
#define NP_KCW  4096
#define N_PREP0 (NP_K1 + NP_KCA + NP_KCW)   // 4480

__device__ __forceinline__ void k1_body(int j, const float* __restrict__ dec,
                                        const float* __restrict__ srch,
                                        const int* __restrict__ mask,
                                        float4* dsm, float* lsum) {
    int b = j >> 1, chunk = j & 1;
    int tid = threadIdx.x;
    const float4* dg = (const float4*)(dec + (size_t)b * LA * H);
    for (int i = tid; i < LA * H / 4; i += 256) dsm[i] = dg[i];
    if (tid < LA) lsum[tid] = 0.f;
    __syncthreads();

    int s = chunk * 158 + tid;
    bool valid = (tid < 158);
    int m = valid ? mask[b * SS + s] : 0;

    float acc[LA];
    #pragma unroll
    for (int l = 0; l < LA; l++) acc[l] = 0.f;

    if (m != 0) {
        const float4* vp = (const float4*)(srch + ((size_t)b * SS + s) * H);
        #pragma unroll 8
        for (int h4 = 0; h4 < H / 4; h4 += 2) {
            float4 v0 = vp[h4], v1 = vp[h4 + 1];
            #pragma unroll
            for (int l = 0; l < LA; l++) {
                float4 d0 = dsm[l * (H / 4) + h4];
                acc[l] += d0.x * v0.x + d0.y * v0.y + d0.z * v0.z + d0.w * v0.w;
                float4 d1 = dsm[l * (H / 4) + h4 + 1];
                acc[l] += d1.x * v1.x + d1.y * v1.y + d1.z * v1.z + d1.w * v1.w;
            }
        }
    }

    #pragma unroll
    for (int l = 0; l < LA; l++) {
        float e = (m != 0) ? __expf(acc[l] * SCALE) : 0.f;
        if (valid) g_copy_exp[(b * LA + l) * SS + s] = e;
        float r = e;
        #pragma unroll
        for (int off = 16; off; off >>= 1) r += __shfl_xor_sync(0xffffffffu, r, off);
        if ((tid & 31) == 0) atomicAdd(&lsum[l], r);
    }
    __syncthreads();
    if (tid < LA) g_rs_copy[(b * 2 + chunk) * LA + tid] = lsum[tid];
}

__device__ __forceinline__ void kcA_body(int j, const float* __restrict__ dec) {
    int i = j * 1024 + threadIdx.x * 4;
    float4 v = *(const float4*)&dec[i];
    __nv_bfloat162 h0, h1;
    h0.x = __float2bfloat16(v.x); h0.y = __float2bfloat16(v.y);
    h1.x = __float2bfloat16(v.z); h1.y = __float2bfloat16(v.w);
    *(__nv_bfloat162*)&g_Abf[i] = h0;
    *(__nv_bfloat162*)&g_Abf[i + 2] = h1;
}

__device__ __forceinline__ void kcW_body(int j, const float* __restrict__ W, float* t) {
    int n0 = (j & 511) * 32, k0 = (j >> 9) * 64;
    int tx = threadIdx.x & 31, ty = threadIdx.x >> 5;
    for (int i = ty; i < 64; i += 8)
        t[i * 33 + tx] = W[(size_t)(k0 + i) * V + n0 + tx];
    __syncthreads();
    for (int i = ty; i < 32; i += 8) {
        __nv_bfloat162 h2;
        h2.x = __float2bfloat16(t[(2 * tx) * 33 + i]);
        h2.y = __float2bfloat16(t[(2 * tx + 1) * 33 + i]);
        *(__nv_bfloat162*)&g_Wt[(size_t)(n0 + i) * H + k0 + 2 * tx] = h2;
    }
}

__global__ __launch_bounds__(256) void k_prep0(const float* __restrict__ dec,
                                               const float* __restrict__ srch,
                                               const int* __restrict__ mask,
                                               const float* __restrict__ W) {
    __shared__ __align__(16) unsigned char usm[16384];
    __shared__ float lsum[LA];
    int bi = blockIdx.x;
    if (bi < NP_K1) {
        k1_body(bi, dec, srch, mask, (float4*)usm, lsum);
    } else if (bi < NP_K1 + NP_KCA) {
        kcA_body(bi - NP_K1, dec);
    } else {
        kcW_body(bi - NP_K1 - NP_KCA, W, (float*)usm);
    }
}

// ---------------- K2: persistent warp-MMA bf16 GEMM -----------------------
#define PITCH 40
#define STG 3
#define TILE_HALFS (128 * PITCH)
#define K2_SMEM (STG * 2 * TILE_HALFS * 2)  // 61440 B
__device__ __forceinline__ void gemm_body(int gid, const float* __restrict__ bias,
                                          __nv_bfloat16* sm) {
    __nv_bfloat16* As = sm;
    __nv_bfloat16* Bs = sm + STG * TILE_HALFS;

    int tid = threadIdx.x, wid = tid >> 5, lane = tid & 31;
    int bx = gid & 127, by = gid >> 7;
    int wm = wid >> 1, wn = wid & 1;

    const __nv_bfloat16* Ag = g_Abf + (size_t)(by * 128) * H;
    const __nv_bfloat16* Bg = g_Wt + (size_t)(bx * 128) * H;

    float acc[4][8][4];
    #pragma unroll
    for (int i = 0; i < 4; i++)
        #pragma unroll
        for (int j = 0; j < 8; j++)
            #pragma unroll
            for (int k = 0; k < 4; k++) acc[i][j][k] = 0.f;

    int ldr = tid >> 2, ldc8 = (tid & 3) * 8;

    #define ISSUE(KT, BUF) do {                                                       \
        _Pragma("unroll")                                                              \
        for (int q = 0; q < 4; q++) {                                                  \
            int _r = ldr + 32 * q;                                                     \
            cp_async16(smem_u32(&As[(BUF) * TILE_HALFS + _r * PITCH + ldc8]),          \
                       Ag + (size_t)_r * H + (KT) * 32 + ldc8);                        \
            cp_async16(smem_u32(&Bs[(BUF) * TILE_HALFS + _r * PITCH + ldc8]),          \
                       Bg + (size_t)_r * H + (KT) * 32 + ldc8);                        \
        }                                                                              \
        CP_COMMIT();                                                                   \
    } while (0)

    ISSUE(0, 0); ISSUE(1, 1);

    int g = lane >> 3, r = lane & 7;
    uint32_t a0[4], b0[4];
    #pragma unroll
    for (int mt = 0; mt < 4; mt++)
        a0[mt] = smem_u32(&As[(wm * 64 + mt * 16 + (g & 1) * 8 + r) * PITCH + (g >> 1) * 8]);
    #pragma unroll
    for (int nq = 0; nq < 4; nq++)
        b0[nq] = smem_u32(&Bs[(wn * 64 + nq * 16 + (g >> 1) * 8 + r) * PITCH + (g & 1) * 8]);

    for (int kt = 0; kt < 16; kt++) {
        if (kt < 15) CP_WAIT(1); else CP_WAIT(0);
        __syncthreads();
        if (kt + 2 < 16) ISSUE(kt + 2, (kt + 2) % STG);

        uint32_t soff = (uint32_t)(kt % STG) * (TILE_HALFS * 2);
        #pragma unroll
        for (int kk = 0; kk < 2; kk++) {
            uint32_t ko = soff + kk * 32;
            uint32_t afr[4][4];
            #pragma unroll
            for (int mt = 0; mt < 4; mt++) ldmx4(afr[mt], a0[mt] + ko);
            uint32_t bfr[4][4];
            #pragma unroll
            for (int nq = 0; nq < 4; nq++) ldmx4(bfr[nq], b0[nq] + ko);
            #pragma unroll
            for (int mt = 0; mt < 4; mt++)
                #pragma unroll
                for (int nt = 0; nt < 8; nt++)
                    mma16816(acc[mt][nt], afr[mt],
                             bfr[nt >> 1][(nt & 1) * 2], bfr[nt >> 1][(nt & 1) * 2 + 1]);
        }
    }
    __syncthreads();   // drain before next tile reuses buffers

    int r4 = lane >> 2, c2 = (lane & 3) * 2;
    #pragma unroll
    for (int mt = 0; mt < 4; mt++) {
        float rs0 = 0.f, rs1 = 0.f;
        #pragma unroll
        for (int nt = 0; nt < 8; nt++) {
            int col = bx * 128 + wn * 64 + nt * 8 + c2;
            float b0f = bias[col], b1f = bias[col + 1];
            int row0 = by * 128 + wm * 64 + mt * 16 + r4;
            float e0 = __expf((acc[mt][nt][0] + b0f) * SCALE);
            float e1 = __expf((acc[mt][nt][1] + b1f) * SCALE);
            *(float2*)&g_gen_exp[(size_t)row0 * V + col] = make_float2(e0, e1);
            rs0 += e0 + e1;
            float e2 = __expf((acc[mt][nt][2] + b0f) * SCALE);
            float e3 = __expf((acc[mt][nt][3] + b1f) * SCALE);
            *(float2*)&g_gen_exp[(size_t)(row0 + 8) * V + col] = make_float2(e2, e3);
            rs1 += e2 + e3;
        }
        #pragma unroll
        for (int off = 1; off < 4; off <<= 1) {
            rs0 += __shfl_xor_sync(0xffffffffu, rs0, off);
            rs1 += __shfl_xor_sync(0xffffffffu, rs1, off);
        }
        if ((lane & 3) == 0) {
            int row0 = by * 128 + wm * 64 + mt * 16 + r4;
            g_rs_gen[row0 * 256 + bx * 2 + wn] = rs0;
            g_rs_gen[(row0 + 8) * 256 + bx * 2 + wn] = rs1;
        }
    }
}

__global__ __launch_bounds__(128) void k2m(const float* __restrict__ bias) {
#if defined(__CUDA_ARCH__) && __CUDA_ARCH__ >= 900
    cudaTriggerProgrammaticLaunchCompletion();   // release PDL secondary ASAP
#endif
    extern __shared__ __align__(16) __nv_bfloat16 sm[];
    for (int t = blockIdx.x; t < N_TILES; t += gridDim.x)
        gemm_body(t, bias, sm);
}

// ---------------- K_scan: PDL-overlapped one-hot scan ---------------------
__global__ __launch_bounds__(256) void k_scan(const float* __restrict__ pv,
                                              const float* __restrict__ lmat,
                                              const float* __restrict__ tpm,
                                              const float* __restrict__ rel) {
    // No cudaGridDependencySynchronize: reads only harness inputs, writes
    // only g_nz/g_nzc — disjoint from k2m. Full concurrency is safe.
    __shared__ int scnt;
    int rid = blockIdx.x;
    int b = rid & (B - 1), row = rid >> 6;
    int tid = threadIdx.x;
    if (tid == 0) scnt = 0;
    __syncthreads();

    const float* base;
    int p, np;
    if (row < 10)      { base = pv;   p = row;      np = 10; }
    else if (row < 20) { base = lmat; p = row - 10; np = 10; }
    else if (row < 30) { base = tpm;  p = row - 20; np = 10; }
    else               { base = rel;  p = row - 30; np = 30; }
    const float* mrow = base + ((size_t)b * np + p) * V;

    #pragma unroll
    for (int q = 0; q < 16; q++) {
        int v4 = q * 256 + tid;
        float4 m = ldcs4(&mrow[(size_t)v4 * 4]);
        float mv[4] = {m.x, m.y, m.z, m.w};
        #pragma unroll
        for (int c = 0; c < 4; c++) {
            if (mv[c] != 0.f) {
                int pos = atomicAdd(&scnt, 1);
                if (pos < MAXNZ)
                    g_nz[rid * MAXNZ + pos] = make_int2(v4 * 4 + c, __float_as_int(mv[c]));
            }
        }
    }
    __syncthreads();
    if (tid == 0) g_nzc[rid] = (scnt < MAXNZ) ? scnt : MAXNZ;
}

// ---------------- K_apply: scatter + invZ reduction -----------------------
__global__ __launch_bounds__(256) void k_apply(const int* __restrict__ ctx,
                                               const int* __restrict__ g2l) {
    int blk = blockIdx.x, tid = threadIdx.x;
    if (blk < 512) {
        int row = blk, b = row >> 3;
        int tgt = g2l[ctx[b * CTXN + tid]];
        atomicAdd(&g_gen_exp[(size_t)row * V + tgt], g_copy_exp[row * SS + 30 + tid]);
    } else if (blk < 632) {
        int j = blk - 512;
        int rid = j * 32 + (tid >> 3);
        int l = tid & 7;
        int b = rid & (B - 1), r60 = rid >> 6;
        int src = (r60 < 30) ? r60 : r60 + CTXN;
        int row = b * LA + l;
        float pc = g_copy_exp[row * SS + src];
        int cnt = g_nzc[rid];
        for (int q = 0; q < cnt; q++) {
            int2 e = g_nz[rid * MAXNZ + q];
            atomicAdd(&g_gen_exp[(size_t)row * V + e.x], pc * __int_as_float(e.y));
        }
    } else {
        int j = blk - 632;
        int wrp = tid >> 5, lane = tid & 31;
        int row = j * 8 + wrp;
        int b = row >> 3, l = row & 7;
        float t = 0.f;
        #pragma unroll
        for (int q = 0; q < 8; q++) t += g_rs_gen[row * 256 + q * 32 + lane];
        if (lane < 2) t += g_rs_copy[(b * 2 + lane) * LA + l];
        #pragma unroll
        for (int off = 16; off; off >>= 1) t += __shfl_xor_sync(0xffffffffu, t, off);
        if (lane == 0) g_rowsum[row] = 1.f / t;
    }
}

// ---------------- K4n: out = g_gen_exp * invZ (PDL, syncs first) ----------
__global__ __launch_bounds__(256) void k4_norm(float* __restrict__ out) {
#if defined(__CUDA_ARCH__) && __CUDA_ARCH__ >= 900
    cudaGridDependencySynchronize();   // wait for k_apply before reading
#endif
    int row = blockIdx.x >> 2, seg = blockIdx.x & 3;
    float z = g_rowsum[row];
    const float* src = &g_gen_exp[(size_t)row * V + seg * (V / 4)];
    float4* dst = (float4*)&out[(size_t)row * V + seg * (V / 4)];
    #pragma unroll
    for (int i = threadIdx.x; i < V / 16; i += 256) {
        float4 v = ldcs4(src + i * 4);
        v.x *= z; v.y *= z; v.z *= z; v.w *= z;
        dst[i] = v;
    }
}

// ---------------- launch --------------------------------------------------
extern "C" void kernel_launch(void* const* d_in, const int* in_sizes, int n_in,
                              void* d_out, int out_size) {
    const float* dec  = (const float*)d_in[0];
    const float* srch = (const float*)d_in[1];
    const int*   mask = (const int*)  d_in[2];
    const float* pv   = (const float*)d_in[3];
    const float* lmat = (const float*)d_in[4];
    const float* tpm  = (const float*)d_in[5];
    const float* rel  = (const float*)d_in[6];
    const float* W    = (const float*)d_in[7];
    const float* bias = (const float*)d_in[8];
    const int*   ctx  = (const int*)  d_in[9];
    const int*   g2l  = (const int*)  d_in[10];
    float* out = (float*)d_out;

    cudaFuncSetAttribute(k2m, cudaFuncAttributeMaxDynamicSharedMemorySize, K2_SMEM);

    k_prep0<<<N_PREP0, 256>>>(dec, srch, mask, W);
    k2m<<<GEMM_GRID, 128, K2_SMEM>>>(bias);

    // k_scan: PDL secondary — runs concurrently with k2m (disjoint data)
    {
        cudaLaunchConfig_t cfg = {};
        cfg.gridDim = dim3(NZROWS * B);
        cfg.blockDim = dim3(256);
        cfg.dynamicSmemBytes = 0;
        cfg.stream = 0;
        cudaLaunchAttribute at[1];
        at[0].id = cudaLaunchAttributeProgrammaticStreamSerialization;
        at[0].val.programmaticStreamSerializationAllowed = 1;
        cfg.attrs = at;
        cfg.numAttrs = 1;
        if (cudaLaunchKernelEx(&cfg, k_scan, pv, lmat, tpm, rel) != cudaSuccess)
            k_scan<<<NZROWS * B, 256>>>(pv, lmat, tpm, rel);
    }

    k_apply<<<696, 256>>>(ctx, g2l);   // full stream order: waits k2m + k_scan

    // k4_norm: PDL to hide launch gap; grid-dep sync inside before reading
    {
        cudaLaunchConfig_t cfg = {};
        cfg.gridDim = dim3(NROWS * 4);
        cfg.blockDim = dim3(256);
        cfg.dynamicSmemBytes = 0;
        cfg.stream = 0;
        cudaLaunchAttribute at[1];
        at[0].id = cudaLaunchAttributeProgrammaticStreamSerialization;
        at[0].val.programmaticStreamSerializationAllowed = 1;
        cfg.attrs = at;
        cfg.numAttrs = 1;
        if (cudaLaunchKernelEx(&cfg, k4_norm, out) != cudaSuccess)
            k4_norm<<<NROWS * 4, 256>>>(out);
    }
}

// round 16
// speedup vs baseline: 2.2197x; 1.1159x over previous
#include <cuda_runtime.h>
#include <cuda_bf16.h>
#include <cstdint>
#include <math.h>

#define B     64
#define LA    8
#define H     512
#define V     16384
#define SS    316
#define CTXN  256
#define NROWS (B*LA)
#define SCALE 0.04419417382415922f   // 512^-0.5
#define NZROWS 60
#define MAXNZ  16
#define N_TILES 512
#define GEMM_GRID 296                // 2 CTAs/SM single wave

// ---------------- device scratch ----------------
__device__ __align__(16) float g_gen_exp[(size_t)NROWS * V];
__device__ float g_copy_exp[NROWS * SS];
__device__ __align__(16) float g_rs_gen[NROWS * 256];
__device__ float g_rs_copy[B * 2 * LA];
__device__ float g_rowsum[NROWS];    // holds 1/Z after k_apply
__device__ __align__(16) __nv_bfloat16 g_Abf[NROWS * H];
__device__ __align__(16) __nv_bfloat16 g_Wt[(size_t)V * H];
__device__ int2 g_nz[NZROWS * B * MAXNZ];
__device__ int  g_nzc[NZROWS * B];

// ---------------- helpers ----------------
__device__ __forceinline__ uint32_t smem_u32(const void* p) {
    uint32_t a;
    asm("{ .reg .u64 t; cvta.to.shared.u64 t, %1; cvt.u32.u64 %0, t; }" : "=r"(a) : "l"(p));
    return a;
}
__device__ __forceinline__ void ldmx4(uint32_t* r, uint32_t addr) {
    asm volatile("ldmatrix.sync.aligned.m8n8.x4.shared.b16 {%0,%1,%2,%3}, [%4];"
        : "=r"(r[0]), "=r"(r[1]), "=r"(r[2]), "=r"(r[3]) : "r"(addr));
}
__device__ __forceinline__ void mma16816(float* d, const uint32_t* a, uint32_t b0, uint32_t b1) {
    asm volatile("mma.sync.aligned.m16n8k16.row.col.f32.bf16.bf16.f32 "
        "{%0,%1,%2,%3}, {%4,%5,%6,%7}, {%8,%9}, {%0,%1,%2,%3};"
        : "+f"(d[0]), "+f"(d[1]), "+f"(d[2]), "+f"(d[3])
        : "r"(a[0]), "r"(a[1]), "r"(a[2]), "r"(a[3]), "r"(b0), "r"(b1));
}
__device__ __forceinline__ void cp_async16(uint32_t dst, const void* src) {
    asm volatile("cp.async.cg.shared.global [%0], [%1], 16;" :: "r"(dst), "l"(src));
}
#define CP_COMMIT() asm volatile("cp.async.commit_group;")
#define CP_WAIT(n)  asm volatile("cp.async.wait_group %0;" :: "n"(n))

__device__ __forceinline__ float4 ldcs4(const float* p) {
    float4 v;
    asm volatile("ld.global.cs.v4.f32 {%0,%1,%2,%3}, [%4];"
        : "=f"(v.x), "=f"(v.y), "=f"(v.z), "=f"(v.w) : "l"(p));
    return v;
}

// ================== PREP0 kernel: kc_A + kc_W + k1 ==================
#define NP_K1   128
#define NP_KCA  256
#define NP_KCW  4096
#define N_PREP0 (NP_K1 + NP_KCA + NP_KCW)   // 4480

__device__ __forceinline__ void k1_body(int j, const float* __restrict__ dec,
                                        const float* __restrict__ srch,
                                        const int* __restrict__ mask,
                                        float4* dsm, float* lsum) {
    int b = j >> 1, chunk = j & 1;
    int tid = threadIdx.x;
    const float4* dg = (const float4*)(dec + (size_t)b * LA * H);
    for (int i = tid; i < LA * H / 4; i += 256) dsm[i] = dg[i];
    if (tid < LA) lsum[tid] = 0.f;
    __syncthreads();

    int s = chunk * 158 + tid;
    bool valid = (tid < 158);
    int m = valid ? mask[b * SS + s] : 0;

    float acc[LA];
    #pragma unroll
    for (int l = 0; l < LA; l++) acc[l] = 0.f;

    if (m != 0) {
        const float4* vp = (const float4*)(srch + ((size_t)b * SS + s) * H);
        #pragma unroll 8
        for (int h4 = 0; h4 < H / 4; h4 += 2) {
            float4 v0 = vp[h4], v1 = vp[h4 + 1];
            #pragma unroll
            for (int l = 0; l < LA; l++) {
                float4 d0 = dsm[l * (H / 4) + h4];
                acc[l] += d0.x * v0.x + d0.y * v0.y + d0.z * v0.z + d0.w * v0.w;
                float4 d1 = dsm[l * (H / 4) + h4 + 1];
                acc[l] += d1.x * v1.x + d1.y * v1.y + d1.z * v1.z + d1.w * v1.w;
            }
        }
    }

    #pragma unroll
    for (int l = 0; l < LA; l++) {
        float e = (m != 0) ? __expf(acc[l] * SCALE) : 0.f;
        if (valid) g_copy_exp[(b * LA + l) * SS + s] = e;
        float r = e;
        #pragma unroll
        for (int off = 16; off; off >>= 1) r += __shfl_xor_sync(0xffffffffu, r, off);
        if ((tid & 31) == 0) atomicAdd(&lsum[l], r);
    }
    __syncthreads();
    if (tid < LA) g_rs_copy[(b * 2 + chunk) * LA + tid] = lsum[tid];
}

__device__ __forceinline__ void kcA_body(int j, const float* __restrict__ dec) {
    int i = j * 1024 + threadIdx.x * 4;
    float4 v = *(const float4*)&dec[i];
    __nv_bfloat162 h0, h1;
    h0.x = __float2bfloat16(v.x); h0.y = __float2bfloat16(v.y);
    h1.x = __float2bfloat16(v.z); h1.y = __float2bfloat16(v.w);
    *(__nv_bfloat162*)&g_Abf[i] = h0;
    *(__nv_bfloat162*)&g_Abf[i + 2] = h1;
}

__device__ __forceinline__ void kcW_body(int j, const float* __restrict__ W, float* t) {
    int n0 = (j & 511) * 32, k0 = (j >> 9) * 64;
    int tx = threadIdx.x & 31, ty = threadIdx.x >> 5;
    for (int i = ty; i < 64; i += 8)
        t[i * 33 + tx] = W[(size_t)(k0 + i) * V + n0 + tx];
    __syncthreads();
    for (int i = ty; i < 32; i += 8) {
        __nv_bfloat162 h2;
        h2.x = __float2bfloat16(t[(2 * tx) * 33 + i]);
        h2.y = __float2bfloat16(t[(2 * tx + 1) * 33 + i]);
        *(__nv_bfloat162*)&g_Wt[(size_t)(n0 + i) * H + k0 + 2 * tx] = h2;
    }
}

__global__ __launch_bounds__(256) void k_prep0(const float* __restrict__ dec,
                                               const float* __restrict__ srch,
                                               const int* __restrict__ mask,
                                               const float* __restrict__ W) {
    __shared__ __align__(16) unsigned char usm[16384];
    __shared__ float lsum[LA];
    int bi = blockIdx.x;
    if (bi < NP_K1) {
        k1_body(bi, dec, srch, mask, (float4*)usm, lsum);
    } else if (bi < NP_K1 + NP_KCA) {
        kcA_body(bi - NP_K1, dec);
    } else {
        kcW_body(bi - NP_K1 - NP_KCA, W, (float*)usm);
    }
}

// ---------------- K2: persistent warp-MMA bf16 GEMM -----------------------
#define PITCH 40
#define STG 3
#define TILE_HALFS (128 * PITCH)
#define K2_SMEM (STG * 2 * TILE_HALFS * 2)  // 61440 B
__device__ __forceinline__ void gemm_body(int gid, const float* __restrict__ bias,
                                          __nv_bfloat16* sm) {
    __nv_bfloat16* As = sm;
    __nv_bfloat16* Bs = sm + STG * TILE_HALFS;

    int tid = threadIdx.x, wid = tid >> 5, lane = tid & 31;
    int bx = gid & 127, by = gid >> 7;
    int wm = wid >> 1, wn = wid & 1;

    const __nv_bfloat16* Ag = g_Abf + (size_t)(by * 128) * H;
    const __nv_bfloat16* Bg = g_Wt + (size_t)(bx * 128) * H;

    float acc[4][8][4];
    #pragma unroll
    for (int i = 0; i < 4; i++)
        #pragma unroll
        for (int j = 0; j < 8; j++)
            #pragma unroll
            for (int k = 0; k < 4; k++) acc[i][j][k] = 0.f;

    int ldr = tid >> 2, ldc8 = (tid & 3) * 8;

    #define ISSUE(KT, BUF) do {                                                       \
        _Pragma("unroll")                                                              \
        for (int q = 0; q < 4; q++) {                                                  \
            int _r = ldr + 32 * q;                                                     \
            cp_async16(smem_u32(&As[(BUF) * TILE_HALFS + _r * PITCH + ldc8]),          \
                       Ag + (size_t)_r * H + (KT) * 32 + ldc8);                        \
            cp_async16(smem_u32(&Bs[(BUF) * TILE_HALFS + _r * PITCH + ldc8]),          \
                       Bg + (size_t)_r * H + (KT) * 32 + ldc8);                        \
        }                                                                              \
        CP_COMMIT();                                                                   \
    } while (0)

    ISSUE(0, 0); ISSUE(1, 1);

    int g = lane >> 3, r = lane & 7;
    uint32_t a0[4], b0[4];
    #pragma unroll
    for (int mt = 0; mt < 4; mt++)
        a0[mt] = smem_u32(&As[(wm * 64 + mt * 16 + (g & 1) * 8 + r) * PITCH + (g >> 1) * 8]);
    #pragma unroll
    for (int nq = 0; nq < 4; nq++)
        b0[nq] = smem_u32(&Bs[(wn * 64 + nq * 16 + (g >> 1) * 8 + r) * PITCH + (g & 1) * 8]);

    for (int kt = 0; kt < 16; kt++) {
        if (kt < 15) CP_WAIT(1); else CP_WAIT(0);
        __syncthreads();
        if (kt + 2 < 16) ISSUE(kt + 2, (kt + 2) % STG);

        uint32_t soff = (uint32_t)(kt % STG) * (TILE_HALFS * 2);
        #pragma unroll
        for (int kk = 0; kk < 2; kk++) {
            uint32_t ko = soff + kk * 32;
            uint32_t afr[4][4];
            #pragma unroll
            for (int mt = 0; mt < 4; mt++) ldmx4(afr[mt], a0[mt] + ko);
            uint32_t bfr[4][4];
            #pragma unroll
            for (int nq = 0; nq < 4; nq++) ldmx4(bfr[nq], b0[nq] + ko);
            #pragma unroll
            for (int mt = 0; mt < 4; mt++)
                #pragma unroll
                for (int nt = 0; nt < 8; nt++)
                    mma16816(acc[mt][nt], afr[mt],
                             bfr[nt >> 1][(nt & 1) * 2], bfr[nt >> 1][(nt & 1) * 2 + 1]);
        }
    }
    __syncthreads();   // drain before next tile reuses buffers

    int r4 = lane >> 2, c2 = (lane & 3) * 2;
    #pragma unroll
    for (int mt = 0; mt < 4; mt++) {
        float rs0 = 0.f, rs1 = 0.f;
        #pragma unroll
        for (int nt = 0; nt < 8; nt++) {
            int col = bx * 128 + wn * 64 + nt * 8 + c2;
            float b0f = bias[col], b1f = bias[col + 1];
            int row0 = by * 128 + wm * 64 + mt * 16 + r4;
            float e0 = __expf((acc[mt][nt][0] + b0f) * SCALE);
            float e1 = __expf((acc[mt][nt][1] + b1f) * SCALE);
            *(float2*)&g_gen_exp[(size_t)row0 * V + col] = make_float2(e0, e1);
            rs0 += e0 + e1;
            float e2 = __expf((acc[mt][nt][2] + b0f) * SCALE);
            float e3 = __expf((acc[mt][nt][3] + b1f) * SCALE);
            *(float2*)&g_gen_exp[(size_t)(row0 + 8) * V + col] = make_float2(e2, e3);
            rs1 += e2 + e3;
        }
        #pragma unroll
        for (int off = 1; off < 4; off <<= 1) {
            rs0 += __shfl_xor_sync(0xffffffffu, rs0, off);
            rs1 += __shfl_xor_sync(0xffffffffu, rs1, off);
        }
        if ((lane & 3) == 0) {
            int row0 = by * 128 + wm * 64 + mt * 16 + r4;
            g_rs_gen[row0 * 256 + bx * 2 + wn] = rs0;
            g_rs_gen[(row0 + 8) * 256 + bx * 2 + wn] = rs1;
        }
    }
}

__global__ __launch_bounds__(128) void k2m(const float* __restrict__ bias) {
#if defined(__CUDA_ARCH__) && __CUDA_ARCH__ >= 900
    cudaTriggerProgrammaticLaunchCompletion();   // release PDL secondary ASAP
#endif
    extern __shared__ __align__(16) __nv_bfloat16 sm[];
    for (int t = blockIdx.x; t < N_TILES; t += gridDim.x)
        gemm_body(t, bias, sm);
}

// ---------------- K_scan: PDL-overlapped one-hot scan (MLP 8) -------------
__global__ __launch_bounds__(256) void k_scan(const float* __restrict__ pv,
                                              const float* __restrict__ lmat,
                                              const float* __restrict__ tpm,
                                              const float* __restrict__ rel) {
    // No cudaGridDependencySynchronize: disjoint from k2m, safe to overlap.
    __shared__ int scnt;
    int rid = blockIdx.x;
    int b = rid & (B - 1), row = rid >> 6;
    int tid = threadIdx.x;
    if (tid == 0) scnt = 0;
    __syncthreads();

    const float* base;
    int p, np;
    if (row < 10)      { base = pv;   p = row;      np = 10; }
    else if (row < 20) { base = lmat; p = row - 10; np = 10; }
    else if (row < 30) { base = tpm;  p = row - 20; np = 10; }
    else               { base = rel;  p = row - 30; np = 30; }
    const float* mrow = base + ((size_t)b * np + p) * V;

    #pragma unroll
    for (int h = 0; h < 2; h++) {
        float4 m[8];
        #pragma unroll
        for (int q = 0; q < 8; q++)
            m[q] = ldcs4(&mrow[(size_t)((h * 8 + q) * 256 + tid) * 4]);
        #pragma unroll
        for (int q = 0; q < 8; q++) {
            if (m[q].x != 0.f || m[q].y != 0.f || m[q].z != 0.f || m[q].w != 0.f) {
                int vb = ((h * 8 + q) * 256 + tid) * 4;
                float mv[4] = {m[q].x, m[q].y, m[q].z, m[q].w};
                #pragma unroll
                for (int c = 0; c < 4; c++) {
                    if (mv[c] != 0.f) {
                        int pos = atomicAdd(&scnt, 1);
                        if (pos < MAXNZ)
                            g_nz[rid * MAXNZ + pos] =
                                make_int2(vb + c, __float_as_int(mv[c]));
                    }
                }
            }
        }
    }
    __syncthreads();
    if (tid == 0) g_nzc[rid] = (scnt < MAXNZ) ? scnt : MAXNZ;
}

// ---------------- K_apply: scatter + invZ reduction (PDL) -----------------
__global__ __launch_bounds__(256) void k_apply(const int* __restrict__ ctx,
                                               const int* __restrict__ g2l) {
#if defined(__CUDA_ARCH__) && __CUDA_ARCH__ >= 900
    cudaGridDependencySynchronize();   // needs k2m + k_scan complete
#endif
    int blk = blockIdx.x, tid = threadIdx.x;
    if (blk < 512) {
        int row = blk, b = row >> 3;
        int tgt = g2l[ctx[b * CTXN + tid]];
        atomicAdd(&g_gen_exp[(size_t)row * V + tgt], g_copy_exp[row * SS + 30 + tid]);
    } else if (blk < 632) {
        int j = blk - 512;
        int rid = j * 32 + (tid >> 3);
        int l = tid & 7;
        int b = rid & (B - 1), r60 = rid >> 6;
        int src = (r60 < 30) ? r60 : r60 + CTXN;
        int row = b * LA + l;
        float pc = g_copy_exp[row * SS + src];
        int cnt = g_nzc[rid];
        for (int q = 0; q < cnt; q++) {
            int2 e = g_nz[rid * MAXNZ + q];
            atomicAdd(&g_gen_exp[(size_t)row * V + e.x], pc * __int_as_float(e.y));
        }
    } else {
        int j = blk - 632;
        int wrp = tid >> 5, lane = tid & 31;
        int row = j * 8 + wrp;
        int b = row >> 3, l = row & 7;
        float t = 0.f;
        #pragma unroll
        for (int q = 0; q < 8; q++) t += g_rs_gen[row * 256 + q * 32 + lane];
        if (lane < 2) t += g_rs_copy[(b * 2 + lane) * LA + l];
        #pragma unroll
        for (int off = 16; off; off >>= 1) t += __shfl_xor_sync(0xffffffffu, t, off);
        if (lane == 0) g_rowsum[row] = 1.f / t;
    }
}

// ---------------- K4n: out = g_gen_exp * invZ (PDL, MLP 4) ----------------
__global__ __launch_bounds__(256) void k4_norm(float* __restrict__ out) {
#if defined(__CUDA_ARCH__) && __CUDA_ARCH__ >= 900
    cudaGridDependencySynchronize();   // wait for k_apply before reading
#endif
    int row = blockIdx.x >> 2, seg = blockIdx.x & 3;
    float z = g_rowsum[row];
    const float* src = &g_gen_exp[(size_t)row * V + seg * (V / 4)];
    float4* dst = (float4*)&out[(size_t)row * V + seg * (V / 4)];
    int tid = threadIdx.x;
    float4 v[4];
    #pragma unroll
    for (int j = 0; j < 4; j++)
        v[j] = ldcs4(src + (tid + j * 256) * 4);
    #pragma unroll
    for (int j = 0; j < 4; j++) {
        v[j].x *= z; v[j].y *= z; v[j].z *= z; v[j].w *= z;
        dst[tid + j * 256] = v[j];
    }
}

// ---------------- launch --------------------------------------------------
static cudaLaunchConfig_t make_pdl_cfg(dim3 grid, dim3 block,
                                       cudaLaunchAttribute* at) {
    cudaLaunchConfig_t cfg = {};
    cfg.gridDim = grid;
    cfg.blockDim = block;
    cfg.dynamicSmemBytes = 0;
    cfg.stream = 0;
    at[0].id = cudaLaunchAttributeProgrammaticStreamSerialization;
    at[0].val.programmaticStreamSerializationAllowed = 1;
    cfg.attrs = at;
    cfg.numAttrs = 1;
    return cfg;
}

extern "C" void kernel_launch(void* const* d_in, const int* in_sizes, int n_in,
                              void* d_out, int out_size) {
    const float* dec  = (const float*)d_in[0];
    const float* srch = (const float*)d_in[1];
    const int*   mask = (const int*)  d_in[2];
    const float* pv   = (const float*)d_in[3];
    const float* lmat = (const float*)d_in[4];
    const float* tpm  = (const float*)d_in[5];
    const float* rel  = (const float*)d_in[6];
    const float* W    = (const float*)d_in[7];
    const float* bias = (const float*)d_in[8];
    const int*   ctx  = (const int*)  d_in[9];
    const int*   g2l  = (const int*)  d_in[10];
    float* out = (float*)d_out;

    cudaFuncSetAttribute(k2m, cudaFuncAttributeMaxDynamicSharedMemorySize, K2_SMEM);

    k_prep0<<<N_PREP0, 256>>>(dec, srch, mask, W);
    k2m<<<GEMM_GRID, 128, K2_SMEM>>>(bias);

    {   // k_scan: PDL secondary — concurrent with k2m (disjoint data)
        cudaLaunchAttribute at[1];
        cudaLaunchConfig_t cfg = make_pdl_cfg(dim3(NZROWS * B), dim3(256), at);
        if (cudaLaunchKernelEx(&cfg, k_scan, pv, lmat, tpm, rel) != cudaSuccess)
            k_scan<<<NZROWS * B, 256>>>(pv, lmat, tpm, rel);
    }
    {   // k_apply: PDL to hide launch gap; grid-dep sync inside
        cudaLaunchAttribute at[1];
        cudaLaunchConfig_t cfg = make_pdl_cfg(dim3(696), dim3(256), at);
        if (cudaLaunchKernelEx(&cfg, k_apply, ctx, g2l) != cudaSuccess)
            k_apply<<<696, 256>>>(ctx, g2l);
    }
    {   // k4_norm: PDL; grid-dep sync inside
        cudaLaunchAttribute at[1];
        cudaLaunchConfig_t cfg = make_pdl_cfg(dim3(NROWS * 4), dim3(256), at);
        if (cudaLaunchKernelEx(&cfg, k4_norm, out) != cudaSuccess)
            k4_norm<<<NROWS * 4, 256>>>(out);
    }
}